// round 5
// baseline (speedup 1.0000x reference)
#include <cuda_runtime.h>
#include <cuda_bf16.h>

// ---------------- problem constants ----------------
#define BB   64
#define NNN  197
#define CC   768
#define HHH  12
#define GHH  2
#define HRR  6
#define DD   64
#define TOTH 16          // 2*GH + H
#define QKVN 1024        // TOTH * D
#define SCALE 0.125f
#define NPAD 199         // padded N for smem rows (stride 199 % 32 = 7, conflict-friendly)
#define NT   4           // query rows per attention CTA

#define MROWS (BB*NNN)   // 12608

// ---------------- device scratch (no allocations allowed) ----------------
__device__ float g_q [BB*GHH*NNN*DD];    // (B,GH,N,D)
__device__ float g_k [BB*GHH*NNN*DD];    // (B,GH,N,D)
__device__ float g_v [BB*HHH*NNN*DD];    // (B,H ,N,D)
__device__ float g_mw[NNN*NNN*HHH];      // (N,N,H)  h fastest
__device__ float g_att[BB*NNN*CC];       // (B,N,C) pre-proj attention output

// ---------------- SGEMM: 128x128 tile, 16-deep K, 256 thr, 8x8 per thread ---
// EPI==0: C[row, col] = acc + bias[col]  (plain, writes C)
// EPI==1: scatter qkv columns into g_q / g_k / g_v (C unused)
template<int EPI>
__global__ __launch_bounds__(256)
void sgemm128(const float* __restrict__ A, const float* __restrict__ Bw,
              const float* __restrict__ bias, float* __restrict__ C,
              int M, int Nc, int K)
{
    __shared__ float As[16*128];   // transposed: As[k][i]
    __shared__ float Bs[16*128];   // Bs[k][j]

    const int tid = threadIdx.x;
    const int rowBase = blockIdx.y * 128;
    const int colBase = blockIdx.x * 128;

    const int a_r = tid >> 2;            // 0..63
    const int a_c = (tid & 3) << 2;      // 0,4,8,12
    const int b_r = tid >> 5;            // 0..7
    const int b_c = (tid & 31) << 2;     // 0..124

    const int tx = tid & 15;             // col group
    const int ty = tid >> 4;             // row group

    float acc[8][8];
    #pragma unroll
    for (int i = 0; i < 8; i++)
        #pragma unroll
        for (int j = 0; j < 8; j++) acc[i][j] = 0.f;

    for (int k0 = 0; k0 < K; k0 += 16) {
        #pragma unroll
        for (int p = 0; p < 2; p++) {
            int r  = a_r + p*64;
            int gr = rowBase + r;
            float4 av = (gr < M) ? *(const float4*)(A + (size_t)gr*K + k0 + a_c)
                                 : make_float4(0.f,0.f,0.f,0.f);
            As[(a_c+0)*128 + r] = av.x;
            As[(a_c+1)*128 + r] = av.y;
            As[(a_c+2)*128 + r] = av.z;
            As[(a_c+3)*128 + r] = av.w;
        }
        #pragma unroll
        for (int p = 0; p < 2; p++) {
            int r = b_r + p*8;
            *(float4*)(Bs + r*128 + b_c) =
                *(const float4*)(Bw + (size_t)(k0 + r)*Nc + colBase + b_c);
        }
        __syncthreads();

        #pragma unroll
        for (int kk = 0; kk < 16; kk++) {
            float ra[8], rb[8];
            #pragma unroll
            for (int i = 0; i < 8; i++) ra[i] = As[kk*128 + ty*8 + i];
            #pragma unroll
            for (int j = 0; j < 8; j++) rb[j] = Bs[kk*128 + tx*8 + j];
            #pragma unroll
            for (int i = 0; i < 8; i++)
                #pragma unroll
                for (int j = 0; j < 8; j++)
                    acc[i][j] = fmaf(ra[i], rb[j], acc[i][j]);
        }
        __syncthreads();
    }

    #pragma unroll
    for (int i = 0; i < 8; i++) {
        int gr = rowBase + ty*8 + i;
        if (gr < M) {
            int bidx = 0, n = 0;
            if (EPI == 1) { bidx = gr / NNN; n = gr % NNN; }
            #pragma unroll
            for (int j = 0; j < 8; j++) {
                int gc = colBase + tx*8 + j;
                float val = acc[i][j] + bias[gc];
                if (EPI == 0) {
                    C[(size_t)gr*Nc + gc] = val;
                } else {
                    int t = gc >> 6, d = gc & 63;
                    if (t < GHH)
                        g_q[(((size_t)bidx*GHH + t)*NNN + n)*DD + d] = val;
                    else if (t < 2*GHH)
                        g_k[(((size_t)bidx*GHH + (t-GHH))*NNN + n)*DD + d] = val;
                    else
                        g_v[(((size_t)bidx*HHH + (t-2*GHH))*NNN + n)*DD + d] = val;
                }
            }
        }
    }
}

// ---------------- mask weights: mw[n,m,h] = masks[n,m,:]@mask_proj[:,h]+base[h]
__global__ void mw_kernel(const float* __restrict__ masks,
                          const float* __restrict__ mproj,
                          const float* __restrict__ mbase)
{
    int idx = blockIdx.x * blockDim.x + threadIdx.x;   // (n*N + m)
    if (idx >= NNN*NNN) return;
    float l0 = masks[(size_t)idx*3 + 0];
    float l1 = masks[(size_t)idx*3 + 1];
    float l2 = masks[(size_t)idx*3 + 2];
    #pragma unroll
    for (int h = 0; h < HHH; h++) {
        g_mw[(size_t)idx*HHH + h] =
            l0*mproj[0*HHH + h] + l1*mproj[1*HHH + h] + l2*mproj[2*HHH + h] + mbase[h];
    }
}

// ---------------- fused attention --------------------------------------------
// CTA = (n-tile of NT rows, batch b). 384 threads = 12 warps.
__global__ __launch_bounds__(384)
void attn_kernel(const float* __restrict__ hpw, const float* __restrict__ hpb)
{
    __shared__ float q_s[NT][GHH][DD];        // 2 KB
    __shared__ float S_s[NT][GHH][NPAD];      // scaled qk dots
    __shared__ float W_s[HHH*HHH];
    __shared__ float hb_s[HHH];
    __shared__ float L_s[NT][HHH][NPAD];      // logits -> probs (in place)

    const int tid  = threadIdx.x;
    const int lane = tid & 31;
    const int warp = tid >> 5;                // 0..11
    const int b    = blockIdx.y;
    const int n0   = blockIdx.x * NT;
    const int nvalid = min(NT, NNN - n0);

    if (tid < HHH*HHH) W_s[tid] = hpw[tid];
    if (tid < HHH)     hb_s[tid] = hpb[tid];

    // load q tile (zero-fill invalid rows -> S becomes 0, logits finite)
    for (int i = tid; i < NT*GHH*DD; i += 384) {
        int nt = i / (GHH*DD), rem = i % (GHH*DD);
        int g = rem / DD, d = rem % DD;
        q_s[nt][g][d] = (nt < nvalid)
            ? g_q[(((size_t)b*GHH + g)*NNN + (n0 + nt))*DD + d] : 0.f;
    }
    __syncthreads();

    // ---- Phase 1a: S[nt][g][m] = SCALE * q[nt,g]·k[b,g,m] ----
    for (int m = warp; m < NNN; m += 12) {
        const float* kb0 = g_k + (((size_t)b*GHH + 0)*NNN + m)*DD;
        const float* kb1 = g_k + (((size_t)b*GHH + 1)*NNN + m)*DD;
        float k00 = kb0[lane], k01 = kb0[lane+32];
        float k10 = kb1[lane], k11 = kb1[lane+32];
        #pragma unroll
        for (int nt = 0; nt < NT; nt++) {
            float p0 = q_s[nt][0][lane]*k00 + q_s[nt][0][lane+32]*k01;
            float p1 = q_s[nt][1][lane]*k10 + q_s[nt][1][lane+32]*k11;
            #pragma unroll
            for (int off = 16; off > 0; off >>= 1) {
                p0 += __shfl_xor_sync(0xffffffffu, p0, off);
                p1 += __shfl_xor_sync(0xffffffffu, p1, off);
            }
            if (lane == 0) {
                S_s[nt][0][m] = p0 * SCALE;
                S_s[nt][1][m] = p1 * SCALE;
            }
        }
    }
    __syncthreads();

    // ---- Phase 1b: per (nt,m) relu(s_g * mw) -> 12x12 head mix -> logits ----
    for (int i = tid; i < NT*NNN; i += 384) {
        int nt = i / NNN, m = i % NNN;
        int n = n0 + nt;
        if (n >= NNN) n = NNN - 1;                 // clamp addr; data already 0 via S
        float s0 = S_s[nt][0][m];
        float s1 = S_s[nt][1][m];
        const float* mwp = g_mw + ((size_t)n*NNN + m)*HHH;
        float r[HHH];
        #pragma unroll
        for (int h = 0; h < HHH; h++) {
            float v = (h < HRR ? s0 : s1) * mwp[h];
            r[h] = v > 0.f ? v : 0.f;
        }
        #pragma unroll
        for (int hp = 0; hp < HHH; hp++) {
            float acc = hb_s[hp];
            #pragma unroll
            for (int h = 0; h < HHH; h++) acc = fmaf(r[h], W_s[h*HHH + hp], acc);
            L_s[nt][hp][m] = acc;
        }
    }
    __syncthreads();

    // ---- Phase 2: softmax over m, one warp per (nt,hp) pair ----
    for (int pair = warp; pair < NT*HHH; pair += 12) {
        int nt = pair / HHH, hp = pair % HHH;
        float* row = L_s[nt][hp];
        float mx = -1e30f;
        for (int m = lane; m < NNN; m += 32) mx = fmaxf(mx, row[m]);
        #pragma unroll
        for (int off = 16; off > 0; off >>= 1)
            mx = fmaxf(mx, __shfl_xor_sync(0xffffffffu, mx, off));
        float sum = 0.f;
        for (int m = lane; m < NNN; m += 32) {
            float e = __expf(row[m] - mx);
            row[m] = e;
            sum += e;
        }
        #pragma unroll
        for (int off = 16; off > 0; off >>= 1)
            sum += __shfl_xor_sync(0xffffffffu, sum, off);
        float inv = 1.f / sum;
        for (int m = lane; m < NNN; m += 32) row[m] *= inv;
    }
    __syncthreads();

    // ---- Phase 3: O[nt][hp][d] = sum_m p[m] * v[b,hp,m,d]; warp = hp ----
    {
        const int hp = warp;
        const float* vb = g_v + (((size_t)b*HHH + hp)*NNN)*DD;
        float acc0[NT], acc1[NT];
        #pragma unroll
        for (int nt = 0; nt < NT; nt++) { acc0[nt] = 0.f; acc1[nt] = 0.f; }
        #pragma unroll 4
        for (int m = 0; m < NNN; m++) {
            float v0 = vb[(size_t)m*DD + lane];
            float v1 = vb[(size_t)m*DD + lane + 32];
            #pragma unroll
            for (int nt = 0; nt < NT; nt++) {
                float p = L_s[nt][hp][m];
                acc0[nt] = fmaf(p, v0, acc0[nt]);
                acc1[nt] = fmaf(p, v1, acc1[nt]);
            }
        }
        for (int nt = 0; nt < nvalid; nt++) {
            float* op = g_att + ((size_t)b*NNN + n0 + nt)*CC + hp*DD;
            op[lane]      = acc0[nt];
            op[lane + 32] = acc1[nt];
        }
    }
}

// ---------------- launcher ----------------------------------------------------
extern "C" void kernel_launch(void* const* d_in, const int* in_sizes, int n_in,
                              void* d_out, int out_size)
{
    const float* x         = (const float*)d_in[0];
    const float* qkv_w     = (const float*)d_in[1];
    const float* qkv_b     = (const float*)d_in[2];
    const float* masks     = (const float*)d_in[3];
    const float* mask_proj = (const float*)d_in[4];
    const float* mask_base = (const float*)d_in[5];
    const float* hpw       = (const float*)d_in[6];
    const float* hpb       = (const float*)d_in[7];
    const float* proj_w    = (const float*)d_in[8];
    const float* proj_b    = (const float*)d_in[9];
    float* out             = (float*)d_out;

    // resolve scratch symbol for proj-GEMM input (host can't decay __device__ arrays)
    void* att_ptr = nullptr;
    cudaGetSymbolAddress(&att_ptr, g_att);

    const int M = MROWS;  // 12608

    // 1) QKV GEMM + scatter into g_q/g_k/g_v
    {
        dim3 grid(QKVN/128, (M + 127)/128);
        sgemm128<1><<<grid, 256>>>(x, qkv_w, qkv_b, nullptr, M, QKVN, CC);
    }
    // 2) mask weights
    mw_kernel<<<(NNN*NNN + 255)/256, 256>>>(masks, mask_proj, mask_base);
    // 3) fused attention -> g_att
    {
        dim3 grid((NNN + NT - 1)/NT, BB);
        attn_kernel<<<grid, 384>>>(hpw, hpb);
    }
    // 4) output projection -> d_out
    {
        dim3 grid(CC/128, (M + 127)/128);
        sgemm128<0><<<grid, 256>>>((const float*)att_ptr, proj_w, proj_b, out, M, CC, CC);
    }
}

// round 6
// speedup vs baseline: 1.0027x; 1.0027x over previous
#include <cuda_runtime.h>
#include <cuda_bf16.h>

// ---------------- problem constants ----------------
#define BB   64
#define NNN  197
#define CC   768
#define HHH  12
#define GHH  2
#define HRR  6
#define DD   64
#define TOTH 16          // 2*GH + H
#define QKVN 1024        // TOTH * D
#define SCALE 0.125f
#define NPAD 199         // padded N for smem rows (stride 199 % 32 = 7, conflict-friendly)
#define NT   4           // query rows per attention CTA

#define MROWS (BB*NNN)   // 12608

// ---------------- device scratch (no allocations allowed) ----------------
__device__ float g_q [BB*GHH*NNN*DD];    // (B,GH,N,D)
__device__ float g_k [BB*GHH*NNN*DD];    // (B,GH,N,D)
__device__ float g_v [BB*HHH*NNN*DD];    // (B,H ,N,D)
__device__ float g_mw[NNN*NNN*HHH];      // (N,N,H)  h fastest
__device__ float g_att[BB*NNN*CC];       // (B,N,C) pre-proj attention output

// ---------------- SGEMM: 128x128 tile, 16-deep K, 256 thr, 8x8 per thread ---
// EPI==0: C[row, col] = acc + bias[col]  (plain, writes C)
// EPI==1: scatter qkv columns into g_q / g_k / g_v (C unused)
template<int EPI>
__global__ __launch_bounds__(256)
void sgemm128(const float* __restrict__ A, const float* __restrict__ Bw,
              const float* __restrict__ bias, float* __restrict__ C,
              int M, int Nc, int K)
{
    __shared__ float As[16*128];   // transposed: As[k][i]
    __shared__ float Bs[16*128];   // Bs[k][j]

    const int tid = threadIdx.x;
    const int rowBase = blockIdx.y * 128;
    const int colBase = blockIdx.x * 128;

    const int a_r = tid >> 2;            // 0..63
    const int a_c = (tid & 3) << 2;      // 0,4,8,12
    const int b_r = tid >> 5;            // 0..7
    const int b_c = (tid & 31) << 2;     // 0..124

    const int tx = tid & 15;             // col group
    const int ty = tid >> 4;             // row group

    float acc[8][8];
    #pragma unroll
    for (int i = 0; i < 8; i++)
        #pragma unroll
        for (int j = 0; j < 8; j++) acc[i][j] = 0.f;

    for (int k0 = 0; k0 < K; k0 += 16) {
        #pragma unroll
        for (int p = 0; p < 2; p++) {
            int r  = a_r + p*64;
            int gr = rowBase + r;
            float4 av = (gr < M) ? *(const float4*)(A + (size_t)gr*K + k0 + a_c)
                                 : make_float4(0.f,0.f,0.f,0.f);
            As[(a_c+0)*128 + r] = av.x;
            As[(a_c+1)*128 + r] = av.y;
            As[(a_c+2)*128 + r] = av.z;
            As[(a_c+3)*128 + r] = av.w;
        }
        #pragma unroll
        for (int p = 0; p < 2; p++) {
            int r = b_r + p*8;
            *(float4*)(Bs + r*128 + b_c) =
                *(const float4*)(Bw + (size_t)(k0 + r)*Nc + colBase + b_c);
        }
        __syncthreads();

        #pragma unroll
        for (int kk = 0; kk < 16; kk++) {
            float ra[8], rb[8];
            #pragma unroll
            for (int i = 0; i < 8; i++) ra[i] = As[kk*128 + ty*8 + i];
            #pragma unroll
            for (int j = 0; j < 8; j++) rb[j] = Bs[kk*128 + tx*8 + j];
            #pragma unroll
            for (int i = 0; i < 8; i++)
                #pragma unroll
                for (int j = 0; j < 8; j++)
                    acc[i][j] = fmaf(ra[i], rb[j], acc[i][j]);
        }
        __syncthreads();
    }

    #pragma unroll
    for (int i = 0; i < 8; i++) {
        int gr = rowBase + ty*8 + i;
        if (gr < M) {
            int bidx = 0, n = 0;
            if (EPI == 1) { bidx = gr / NNN; n = gr % NNN; }
            #pragma unroll
            for (int j = 0; j < 8; j++) {
                int gc = colBase + tx*8 + j;
                float val = acc[i][j] + bias[gc];
                if (EPI == 0) {
                    C[(size_t)gr*Nc + gc] = val;
                } else {
                    int t = gc >> 6, d = gc & 63;
                    if (t < GHH)
                        g_q[(((size_t)bidx*GHH + t)*NNN + n)*DD + d] = val;
                    else if (t < 2*GHH)
                        g_k[(((size_t)bidx*GHH + (t-GHH))*NNN + n)*DD + d] = val;
                    else
                        g_v[(((size_t)bidx*HHH + (t-2*GHH))*NNN + n)*DD + d] = val;
                }
            }
        }
    }
}

// ---------------- mask weights: mw[n,m,h] = masks[n,m,:]@mask_proj[:,h]+base[h]
__global__ void mw_kernel(const float* __restrict__ masks,
                          const float* __restrict__ mproj,
                          const float* __restrict__ mbase)
{
    int idx = blockIdx.x * blockDim.x + threadIdx.x;   // (n*N + m)
    if (idx >= NNN*NNN) return;
    float l0 = masks[(size_t)idx*3 + 0];
    float l1 = masks[(size_t)idx*3 + 1];
    float l2 = masks[(size_t)idx*3 + 2];
    #pragma unroll
    for (int h = 0; h < HHH; h++) {
        g_mw[(size_t)idx*HHH + h] =
            l0*mproj[0*HHH + h] + l1*mproj[1*HHH + h] + l2*mproj[2*HHH + h] + mbase[h];
    }
}

// ---------------- fused attention --------------------------------------------
// CTA = (n-tile of NT rows, batch b). 384 threads = 12 warps.
__global__ __launch_bounds__(384)
void attn_kernel(const float* __restrict__ hpw, const float* __restrict__ hpb)
{
    __shared__ float q_s[NT][GHH][DD];        // 2 KB
    __shared__ float S_s[NT][GHH][NPAD];      // scaled qk dots
    __shared__ float W_s[HHH*HHH];
    __shared__ float hb_s[HHH];
    __shared__ float L_s[NT][HHH][NPAD];      // logits -> probs (in place)

    const int tid  = threadIdx.x;
    const int lane = tid & 31;
    const int warp = tid >> 5;                // 0..11
    const int b    = blockIdx.y;
    const int n0   = blockIdx.x * NT;
    const int nvalid = min(NT, NNN - n0);

    if (tid < HHH*HHH) W_s[tid] = hpw[tid];
    if (tid < HHH)     hb_s[tid] = hpb[tid];

    // load q tile (zero-fill invalid rows -> S becomes 0, logits finite)
    for (int i = tid; i < NT*GHH*DD; i += 384) {
        int nt = i / (GHH*DD), rem = i % (GHH*DD);
        int g = rem / DD, d = rem % DD;
        q_s[nt][g][d] = (nt < nvalid)
            ? g_q[(((size_t)b*GHH + g)*NNN + (n0 + nt))*DD + d] : 0.f;
    }
    __syncthreads();

    // ---- Phase 1a: S[nt][g][m] = SCALE * q[nt,g]·k[b,g,m] ----
    for (int m = warp; m < NNN; m += 12) {
        const float* kb0 = g_k + (((size_t)b*GHH + 0)*NNN + m)*DD;
        const float* kb1 = g_k + (((size_t)b*GHH + 1)*NNN + m)*DD;
        float k00 = kb0[lane], k01 = kb0[lane+32];
        float k10 = kb1[lane], k11 = kb1[lane+32];
        #pragma unroll
        for (int nt = 0; nt < NT; nt++) {
            float p0 = q_s[nt][0][lane]*k00 + q_s[nt][0][lane+32]*k01;
            float p1 = q_s[nt][1][lane]*k10 + q_s[nt][1][lane+32]*k11;
            #pragma unroll
            for (int off = 16; off > 0; off >>= 1) {
                p0 += __shfl_xor_sync(0xffffffffu, p0, off);
                p1 += __shfl_xor_sync(0xffffffffu, p1, off);
            }
            if (lane == 0) {
                S_s[nt][0][m] = p0 * SCALE;
                S_s[nt][1][m] = p1 * SCALE;
            }
        }
    }
    __syncthreads();

    // ---- Phase 1b: per (nt,m) relu(s_g * mw) -> 12x12 head mix -> logits ----
    for (int i = tid; i < NT*NNN; i += 384) {
        int nt = i / NNN, m = i % NNN;
        int n = n0 + nt;
        if (n >= NNN) n = NNN - 1;                 // clamp addr; data already 0 via S
        float s0 = S_s[nt][0][m];
        float s1 = S_s[nt][1][m];
        const float* mwp = g_mw + ((size_t)n*NNN + m)*HHH;
        float r[HHH];
        #pragma unroll
        for (int h = 0; h < HHH; h++) {
            float v = (h < HRR ? s0 : s1) * mwp[h];
            r[h] = v > 0.f ? v : 0.f;
        }
        #pragma unroll
        for (int hp = 0; hp < HHH; hp++) {
            float acc = hb_s[hp];
            #pragma unroll
            for (int h = 0; h < HHH; h++) acc = fmaf(r[h], W_s[h*HHH + hp], acc);
            L_s[nt][hp][m] = acc;
        }
    }
    __syncthreads();

    // ---- Phase 2: softmax over m, one warp per (nt,hp) pair ----
    for (int pair = warp; pair < NT*HHH; pair += 12) {
        int nt = pair / HHH, hp = pair % HHH;
        float* row = L_s[nt][hp];
        float mx = -1e30f;
        for (int m = lane; m < NNN; m += 32) mx = fmaxf(mx, row[m]);
        #pragma unroll
        for (int off = 16; off > 0; off >>= 1)
            mx = fmaxf(mx, __shfl_xor_sync(0xffffffffu, mx, off));
        float sum = 0.f;
        for (int m = lane; m < NNN; m += 32) {
            float e = __expf(row[m] - mx);
            row[m] = e;
            sum += e;
        }
        #pragma unroll
        for (int off = 16; off > 0; off >>= 1)
            sum += __shfl_xor_sync(0xffffffffu, sum, off);
        float inv = 1.f / sum;
        for (int m = lane; m < NNN; m += 32) row[m] *= inv;
    }
    __syncthreads();

    // ---- Phase 3: O[nt][hp][d] = sum_m p[m] * v[b,hp,m,d]; warp = hp ----
    {
        const int hp = warp;
        const float* vb = g_v + (((size_t)b*HHH + hp)*NNN)*DD;
        float acc0[NT], acc1[NT];
        #pragma unroll
        for (int nt = 0; nt < NT; nt++) { acc0[nt] = 0.f; acc1[nt] = 0.f; }
        #pragma unroll 4
        for (int m = 0; m < NNN; m++) {
            float v0 = vb[(size_t)m*DD + lane];
            float v1 = vb[(size_t)m*DD + lane + 32];
            #pragma unroll
            for (int nt = 0; nt < NT; nt++) {
                float p = L_s[nt][hp][m];
                acc0[nt] = fmaf(p, v0, acc0[nt]);
                acc1[nt] = fmaf(p, v1, acc1[nt]);
            }
        }
        for (int nt = 0; nt < nvalid; nt++) {
            float* op = g_att + ((size_t)b*NNN + n0 + nt)*CC + hp*DD;
            op[lane]      = acc0[nt];
            op[lane + 32] = acc1[nt];
        }
    }
}

// ---------------- launcher ----------------------------------------------------
extern "C" void kernel_launch(void* const* d_in, const int* in_sizes, int n_in,
                              void* d_out, int out_size)
{
    const float* x         = (const float*)d_in[0];
    const float* qkv_w     = (const float*)d_in[1];
    const float* qkv_b     = (const float*)d_in[2];
    const float* masks     = (const float*)d_in[3];
    const float* mask_proj = (const float*)d_in[4];
    const float* mask_base = (const float*)d_in[5];
    const float* hpw       = (const float*)d_in[6];
    const float* hpb       = (const float*)d_in[7];
    const float* proj_w    = (const float*)d_in[8];
    const float* proj_b    = (const float*)d_in[9];
    float* out             = (float*)d_out;

    // resolve scratch symbol for proj-GEMM input (host can't decay __device__ arrays)
    void* att_ptr = nullptr;
    cudaGetSymbolAddress(&att_ptr, g_att);

    const int M = MROWS;  // 12608

    // 1) QKV GEMM + scatter into g_q/g_k/g_v
    {
        dim3 grid(QKVN/128, (M + 127)/128);
        sgemm128<1><<<grid, 256>>>(x, qkv_w, qkv_b, nullptr, M, QKVN, CC);
    }
    // 2) mask weights
    mw_kernel<<<(NNN*NNN + 255)/256, 256>>>(masks, mask_proj, mask_base);
    // 3) fused attention -> g_att
    {
        dim3 grid((NNN + NT - 1)/NT, BB);
        attn_kernel<<<grid, 384>>>(hpw, hpb);
    }
    // 4) output projection -> d_out
    {
        dim3 grid(CC/128, (M + 127)/128);
        sgemm128<0><<<grid, 256>>>((const float*)att_ptr, proj_w, proj_b, out, M, CC, CC);
    }
}